// round 2
// baseline (speedup 1.0000x reference)
#include <cuda_runtime.h>
#include <math.h>

// Problem constants
#define BATCH 8192
#define TT    128     // T
#define FF    63      // F
#define HH    128     // H
#define PP    64      // P (steps)
#define GG    512     // 4*H gates
#define II    64      // input width = 1 + F

#define MROWS    64                 // batch rows per block
#define NTHREADS 512
#define NBLOCKS  (BATCH / MROWS)    // 128

// One-time scratch: k-major combined weights Wt[k][g], k in [0,192):
//   k < 64   -> W_ih[g][k]   (k=0 is the recurrent-out column)
//   k >= 64  -> W_hh[g][k-64]
__device__ float g_Wt[192 * 512];
__device__ float g_bsum[512];

__global__ void setup_kernel(const float* __restrict__ Wih,
                             const float* __restrict__ Whh,
                             const float* __restrict__ bih,
                             const float* __restrict__ bhh) {
    int k = blockIdx.x;      // 0..191
    int g = threadIdx.x;     // 0..511
    float v = (k < II) ? Wih[g * II + k] : Whh[g * HH + (k - II)];
    g_Wt[k * GG + g] = v;
    if (k == 0) g_bsum[g] = bih[g] + bhh[g];
}

__device__ __forceinline__ float sigf(float v) {
    return 1.0f / (1.0f + expf(-v));
}

// Persistent LSTM: each block owns MROWS batch rows for all PP steps.
// Thread tile: 4 rows x 4 j-cols x 4 gate types (i,f,g,o) -> c stays in regs.
// Mapping: lane%16 -> row-group (rows vary across lanes -> coalesced/broadcast-
// free W LDG, swizzled LDS); warp*2 + lane/16 -> j-group (distinct W data per
// warp -> no redundant L1tex wavefronts).
__global__ __launch_bounds__(NTHREADS, 1)
void lstm_kernel(const float* __restrict__ x,
                 const float* __restrict__ z,
                 const float* __restrict__ h0,
                 const float* __restrict__ c0,
                 const float* __restrict__ Wout,
                 const float* __restrict__ bout,
                 float* __restrict__ Y) {
    // XOR-swizzled tiles: addr(row, col) = row*stride + (col ^ (row & 31))
    __shared__ float inp_s[MROWS * 64];    // 16 KB  (col 0 = recurrent out)
    __shared__ float h_s[MROWS * 128];     // 32 KB

    const int tid  = threadIdx.x;
    const int b0   = blockIdx.x * MROWS;
    const int w    = tid >> 5;
    const int lane = tid & 31;
    const int rg   = lane & 15;                 // 0..15
    const int jg   = (w << 1) | (lane >> 4);    // 0..31
    const int row0 = rg << 2;                   // 0..60
    const int j0   = jg << 2;                   // 0..124

    // ---- init h_s from h0 (swizzled) ----
    for (int idx = tid; idx < MROWS * HH; idx += NTHREADS) {
        int r = idx >> 7, k = idx & 127;
        h_s[r * 128 + (k ^ (r & 31))] = h0[(b0 + r) * HH + k];
    }
    // ---- init recurrent-out column from x[:, T-1, 0] ----
    for (int r = tid; r < MROWS; r += NTHREADS) {
        inp_s[r * 64 + (r & 31)] = x[(b0 + r) * TT + (TT - 1)];
    }
    // ---- c state lives in registers for the whole recurrence ----
    float c[4][4];
    #pragma unroll
    for (int rr = 0; rr < 4; rr++)
        #pragma unroll
        for (int jj = 0; jj < 4; jj++)
            c[rr][jj] = c0[(b0 + row0 + rr) * HH + (j0 + jj)];

    for (int t = 0; t < PP; t++) {
        // ---- stream this step's z features into inp_s cols 1..63 ----
        for (int idx = tid; idx < MROWS * FF; idx += NTHREADS) {
            int r = idx / FF;
            int f = idx - r * FF;
            inp_s[r * 64 + ((1 + f) ^ (r & 31))] =
                z[((b0 + r) * TT + (TT - PP + t)) * FF + f];
        }
        __syncthreads();

        // ---- gates GEMM: acc[row][type][j] over k = 0..191 ----
        float acc[4][4][4];
        #pragma unroll
        for (int rr = 0; rr < 4; rr++)
            #pragma unroll
            for (int ty = 0; ty < 4; ty++)
                #pragma unroll
                for (int jj = 0; jj < 4; jj++)
                    acc[rr][ty][jj] = 0.0f;

        // input part (k in [0,64): col 0 = prev out, cols 1..63 = z)
        #pragma unroll 4
        for (int k = 0; k < II; k++) {
            const float* wr = &g_Wt[k * GG];
            float4 wv[4];
            #pragma unroll
            for (int ty = 0; ty < 4; ty++)
                wv[ty] = *(const float4*)&wr[ty * 128 + j0];
            float v[4];
            #pragma unroll
            for (int rr = 0; rr < 4; rr++) {
                int row = row0 + rr;
                v[rr] = inp_s[row * 64 + (k ^ (row & 31))];
            }
            #pragma unroll
            for (int rr = 0; rr < 4; rr++)
                #pragma unroll
                for (int ty = 0; ty < 4; ty++) {
                    acc[rr][ty][0] += v[rr] * wv[ty].x;
                    acc[rr][ty][1] += v[rr] * wv[ty].y;
                    acc[rr][ty][2] += v[rr] * wv[ty].z;
                    acc[rr][ty][3] += v[rr] * wv[ty].w;
                }
        }
        // hidden part (k in [0,128))
        #pragma unroll 4
        for (int k = 0; k < HH; k++) {
            const float* wr = &g_Wt[(II + k) * GG];
            float4 wv[4];
            #pragma unroll
            for (int ty = 0; ty < 4; ty++)
                wv[ty] = *(const float4*)&wr[ty * 128 + j0];
            float v[4];
            #pragma unroll
            for (int rr = 0; rr < 4; rr++) {
                int row = row0 + rr;
                v[rr] = h_s[row * 128 + (k ^ (row & 31))];
            }
            #pragma unroll
            for (int rr = 0; rr < 4; rr++)
                #pragma unroll
                for (int ty = 0; ty < 4; ty++) {
                    acc[rr][ty][0] += v[rr] * wv[ty].x;
                    acc[rr][ty][1] += v[rr] * wv[ty].y;
                    acc[rr][ty][2] += v[rr] * wv[ty].z;
                    acc[rr][ty][3] += v[rr] * wv[ty].w;
                }
        }
        __syncthreads();   // everyone done reading h_s / inp_s

        // ---- pointwise LSTM cell update; write new h into h_s ----
        #pragma unroll
        for (int rr = 0; rr < 4; rr++) {
            int row = row0 + rr;
            #pragma unroll
            for (int jj = 0; jj < 4; jj++) {
                int j = j0 + jj;
                float gi = acc[rr][0][jj] + __ldg(&g_bsum[0 * 128 + j]);
                float gf = acc[rr][1][jj] + __ldg(&g_bsum[1 * 128 + j]);
                float gg = acc[rr][2][jj] + __ldg(&g_bsum[2 * 128 + j]);
                float go = acc[rr][3][jj] + __ldg(&g_bsum[3 * 128 + j]);
                float cn = sigf(gf) * c[rr][jj] + sigf(gi) * tanhf(gg);
                c[rr][jj] = cn;
                float hv = sigf(go) * tanhf(cn);
                h_s[row * 128 + (j ^ (row & 31))] = hv;
            }
        }
        __syncthreads();   // h_s complete

        // ---- out = h @ W_out.T + b_out : one thread per batch row ----
        if (tid < MROWS) {
            int r = tid;
            float s = 0.0f;
            #pragma unroll 8
            for (int k = 0; k < HH; k++)
                s += h_s[r * 128 + (k ^ (r & 31))] * __ldg(&Wout[k]);
            s += __ldg(&bout[0]);
            inp_s[r * 64 + (r & 31)] = s;            // recurrent input, next step
            Y[(b0 + r) * PP + t] = s;                // output (B, P, 1)
        }
        __syncthreads();
    }
}

extern "C" void kernel_launch(void* const* d_in, const int* in_sizes, int n_in,
                              void* d_out, int out_size) {
    const float* x    = (const float*)d_in[0];
    const float* z    = (const float*)d_in[1];
    const float* h0   = (const float*)d_in[2];
    const float* c0   = (const float*)d_in[3];
    const float* Wih  = (const float*)d_in[4];
    const float* Whh  = (const float*)d_in[5];
    const float* bih  = (const float*)d_in[6];
    const float* bhh  = (const float*)d_in[7];
    const float* Wout = (const float*)d_in[8];
    const float* bout = (const float*)d_in[9];
    float* Y = (float*)d_out;

    setup_kernel<<<192, 512>>>(Wih, Whh, bih, bhh);
    lstm_kernel<<<NBLOCKS, NTHREADS>>>(x, z, h0, c0, Wout, bout, Y);
}

// round 4
// speedup vs baseline: 1.0005x; 1.0005x over previous
#include <cuda_runtime.h>
#include <math.h>

// Problem constants
#define BATCH 8192
#define TT    128     // T
#define FF    63      // F
#define HH    128     // H
#define PP    64      // P (steps)
#define GG    512     // 4*H gates
#define II    64      // input width = 1 + F

#define MROWS    64                 // batch rows per block
#define NTHREADS 512
#define NBLOCKS  (BATCH / MROWS)    // 128

// One-time scratch: k-major combined weights Wt[k][g], k in [0,192):
//   k < 64   -> W_ih[g][k]   (k=0 is the recurrent-out column)
//   k >= 64  -> W_hh[g][k-64]
__device__ float g_Wt[192 * 512];
__device__ float g_bsum[512];

__global__ void setup_kernel(const float* __restrict__ Wih,
                             const float* __restrict__ Whh,
                             const float* __restrict__ bih,
                             const float* __restrict__ bhh) {
    int k = blockIdx.x;      // 0..191
    int g = threadIdx.x;     // 0..511
    float v = (k < II) ? Wih[g * II + k] : Whh[g * HH + (k - II)];
    g_Wt[k * GG + g] = v;
    if (k == 0) g_bsum[g] = bih[g] + bhh[g];
}

__device__ __forceinline__ float sigf(float v) {
    return 1.0f / (1.0f + expf(-v));
}

// Persistent LSTM: each block owns MROWS batch rows for all PP steps.
// Thread tile: 4 rows x 4 j-cols x 4 gate types (i,f,g,o) -> c stays in regs.
// Mapping: lane%16 -> row-group (rows vary across lanes -> coalesced/broadcast-
// free W LDG, swizzled LDS); warp*2 + lane/16 -> j-group (distinct W data per
// warp -> no redundant L1tex wavefronts).
__global__ __launch_bounds__(NTHREADS, 1)
void lstm_kernel(const float* __restrict__ x,
                 const float* __restrict__ z,
                 const float* __restrict__ h0,
                 const float* __restrict__ c0,
                 const float* __restrict__ Wout,
                 const float* __restrict__ bout,
                 float* __restrict__ Y) {
    // XOR-swizzled tiles: addr(row, col) = row*stride + (col ^ (row & 31))
    __shared__ float inp_s[MROWS * 64];    // 16 KB  (col 0 = recurrent out)
    __shared__ float h_s[MROWS * 128];     // 32 KB

    const int tid  = threadIdx.x;
    const int b0   = blockIdx.x * MROWS;
    const int w    = tid >> 5;
    const int lane = tid & 31;
    const int rg   = lane & 15;                 // 0..15
    const int jg   = (w << 1) | (lane >> 4);    // 0..31
    const int row0 = rg << 2;                   // 0..60
    const int j0   = jg << 2;                   // 0..124

    // ---- init h_s from h0 (swizzled) ----
    for (int idx = tid; idx < MROWS * HH; idx += NTHREADS) {
        int r = idx >> 7, k = idx & 127;
        h_s[r * 128 + (k ^ (r & 31))] = h0[(b0 + r) * HH + k];
    }
    // ---- init recurrent-out column from x[:, T-1, 0] ----
    for (int r = tid; r < MROWS; r += NTHREADS) {
        inp_s[r * 64 + (r & 31)] = x[(b0 + r) * TT + (TT - 1)];
    }
    // ---- c state lives in registers for the whole recurrence ----
    float c[4][4];
    #pragma unroll
    for (int rr = 0; rr < 4; rr++)
        #pragma unroll
        for (int jj = 0; jj < 4; jj++)
            c[rr][jj] = c0[(b0 + row0 + rr) * HH + (j0 + jj)];

    for (int t = 0; t < PP; t++) {
        // ---- stream this step's z features into inp_s cols 1..63 ----
        for (int idx = tid; idx < MROWS * FF; idx += NTHREADS) {
            int r = idx / FF;
            int f = idx - r * FF;
            inp_s[r * 64 + ((1 + f) ^ (r & 31))] =
                z[((b0 + r) * TT + (TT - PP + t)) * FF + f];
        }
        __syncthreads();

        // ---- gates GEMM: acc[row][type][j] over k = 0..191 ----
        float acc[4][4][4];
        #pragma unroll
        for (int rr = 0; rr < 4; rr++)
            #pragma unroll
            for (int ty = 0; ty < 4; ty++)
                #pragma unroll
                for (int jj = 0; jj < 4; jj++)
                    acc[rr][ty][jj] = 0.0f;

        // input part (k in [0,64): col 0 = prev out, cols 1..63 = z)
        #pragma unroll 4
        for (int k = 0; k < II; k++) {
            const float* wr = &g_Wt[k * GG];
            float4 wv[4];
            #pragma unroll
            for (int ty = 0; ty < 4; ty++)
                wv[ty] = *(const float4*)&wr[ty * 128 + j0];
            float v[4];
            #pragma unroll
            for (int rr = 0; rr < 4; rr++) {
                int row = row0 + rr;
                v[rr] = inp_s[row * 64 + (k ^ (row & 31))];
            }
            #pragma unroll
            for (int rr = 0; rr < 4; rr++)
                #pragma unroll
                for (int ty = 0; ty < 4; ty++) {
                    acc[rr][ty][0] += v[rr] * wv[ty].x;
                    acc[rr][ty][1] += v[rr] * wv[ty].y;
                    acc[rr][ty][2] += v[rr] * wv[ty].z;
                    acc[rr][ty][3] += v[rr] * wv[ty].w;
                }
        }
        // hidden part (k in [0,128))
        #pragma unroll 4
        for (int k = 0; k < HH; k++) {
            const float* wr = &g_Wt[(II + k) * GG];
            float4 wv[4];
            #pragma unroll
            for (int ty = 0; ty < 4; ty++)
                wv[ty] = *(const float4*)&wr[ty * 128 + j0];
            float v[4];
            #pragma unroll
            for (int rr = 0; rr < 4; rr++) {
                int row = row0 + rr;
                v[rr] = h_s[row * 128 + (k ^ (row & 31))];
            }
            #pragma unroll
            for (int rr = 0; rr < 4; rr++)
                #pragma unroll
                for (int ty = 0; ty < 4; ty++) {
                    acc[rr][ty][0] += v[rr] * wv[ty].x;
                    acc[rr][ty][1] += v[rr] * wv[ty].y;
                    acc[rr][ty][2] += v[rr] * wv[ty].z;
                    acc[rr][ty][3] += v[rr] * wv[ty].w;
                }
        }
        __syncthreads();   // everyone done reading h_s / inp_s

        // ---- pointwise LSTM cell update; write new h into h_s ----
        #pragma unroll
        for (int rr = 0; rr < 4; rr++) {
            int row = row0 + rr;
            #pragma unroll
            for (int jj = 0; jj < 4; jj++) {
                int j = j0 + jj;
                float gi = acc[rr][0][jj] + __ldg(&g_bsum[0 * 128 + j]);
                float gf = acc[rr][1][jj] + __ldg(&g_bsum[1 * 128 + j]);
                float gg = acc[rr][2][jj] + __ldg(&g_bsum[2 * 128 + j]);
                float go = acc[rr][3][jj] + __ldg(&g_bsum[3 * 128 + j]);
                float cn = sigf(gf) * c[rr][jj] + sigf(gi) * tanhf(gg);
                c[rr][jj] = cn;
                float hv = sigf(go) * tanhf(cn);
                h_s[row * 128 + (j ^ (row & 31))] = hv;
            }
        }
        __syncthreads();   // h_s complete

        // ---- out = h @ W_out.T + b_out : one thread per batch row ----
        if (tid < MROWS) {
            int r = tid;
            float s = 0.0f;
            #pragma unroll 8
            for (int k = 0; k < HH; k++)
                s += h_s[r * 128 + (k ^ (r & 31))] * __ldg(&Wout[k]);
            s += __ldg(&bout[0]);
            inp_s[r * 64 + (r & 31)] = s;            // recurrent input, next step
            Y[(b0 + r) * PP + t] = s;                // output (B, P, 1)
        }
        __syncthreads();
    }
}

extern "C" void kernel_launch(void* const* d_in, const int* in_sizes, int n_in,
                              void* d_out, int out_size) {
    const float* x    = (const float*)d_in[0];
    const float* z    = (const float*)d_in[1];
    const float* h0   = (const float*)d_in[2];
    const float* c0   = (const float*)d_in[3];
    const float* Wih  = (const float*)d_in[4];
    const float* Whh  = (const float*)d_in[5];
    const float* bih  = (const float*)d_in[6];
    const float* bhh  = (const float*)d_in[7];
    const float* Wout = (const float*)d_in[8];
    const float* bout = (const float*)d_in[9];
    float* Y = (float*)d_out;

    setup_kernel<<<192, 512>>>(Wih, Whh, bih, bhh);
    lstm_kernel<<<NBLOCKS, NTHREADS>>>(x, z, h0, c0, Wout, bout, Y);
}